// round 15
// baseline (speedup 1.0000x reference)
#include <cuda_runtime.h>
#include <math.h>

#define NMODES      6400
#define TPB         256           // threads per block (8 warps)
#define NBLK        592           // 4 blocks/SM * 148 SMs -> wave-1 co-resident
#define NBP1        25            // blocks that own modes (25*256 = 6400)
#define NWARP       8
#define NCNT        8             // distributed barrier counters
#define BPC         (NBLK / NCNT) // blocks per counter = 74
#define NBINS       260           // lifetime bins (0..258)
#define CHUNK       512           // samples per warp-chunk = 32 lanes * U
#define U           16            // accumulators per lane
#define G           64            // mode groups (warp granularity)
#define GR          8             // partial buffers (one per 8-group octet)
#define MAX_SAMPLES 132096
#define MAX_CHUNKS  258
#define TLN         18.0f         // -ln(~1.5e-8) relative amplitude cutoff

// Static scratch (no runtime allocation allowed)
__device__ float4       g_uA[NMODES], g_uB[NMODES];   // unsorted per-mode params
__device__ int          g_Lm[NMODES];                 // lifetime in chunks
__device__ int          g_hist2[NBINS][NBP1];
__device__ int          g_cnt[MAX_CHUNKS];            // #active modes at chunk c
__device__ float4       g_pA[NMODES], g_pB[NMODES];   // lifetime-sorted params
__device__ float        g_partial[(size_t)GR * MAX_SAMPLES];
__device__ unsigned int g_maxbits;
__device__ volatile unsigned int g_ctr[NCNT];         // barrier counters (monotonic)

__device__ __forceinline__ float softplusf(float x) {
    return (x > 20.f) ? x : log1pf(expf(x));
}

// 2pi split for Cody-Waite (compile-time constants)
#define INV2PI 0.15915494309189535f
#define P2_0   6.28125f
#define P2_1   ((float)(6.283185307179586476925 - 6.28125))
#define P2_2   ((float)(6.283185307179586476925 - 6.28125 \
                        - (double)(float)(6.283185307179586476925 - 6.28125)))

// ---------------------------------------------------------------------------
// Megakernel v2: p1 -> p3 -> modal -> reduce+norm. 592 co-resident blocks.
// ---------------------------------------------------------------------------
__global__ void __launch_bounds__(TPB, 4) mega_kernel(
    const float* mu_raw, const float* D_raw, const float* T0_raw,
    const float* Ly_raw, const float* xo_raw, const float* yo_raw,
    float* out, int N, int nchunks)
{
    __shared__ float shf[NWARP][CHUNK];   // 16 KB: modal combine / p3 wcnt
    __shared__ int   offL[NBINS];
    __shared__ int   preB[NBINS];
    __shared__ int   sh_hist[NBINS];
    __shared__ float wmax[NWARP];
    __shared__ unsigned int sh_tgt;

    const int tid  = threadIdx.x;
    const int b    = blockIdx.x;
    const int wid  = tid >> 5;
    const int lane = tid & 31;

    // Distributed grid barrier. All NBLK blocks arrive (1 atomic each, spread
    // over NCNT counters, BPC arrivals per counter per barrier instance).
    // Barrier instances are globally serialized (no block enters instance k+1
    // before instance k completes), so (old/BPC+1)*BPC is the instance target
    // for ALL counters — correct across graph replays (counters monotonic).
    auto grid_barrier = [&]() {
        __threadfence();
        __syncthreads();
        if (tid == 0) {
            unsigned int old = atomicAdd((unsigned int*)&g_ctr[b & (NCNT - 1)], 1u);
            sh_tgt = (old / BPC + 1u) * BPC;
        }
        __syncthreads();
        if (tid < NCNT) {
            unsigned int t = sh_tgt;
            while (g_ctr[tid] < t) { }
        }
        __syncthreads();
    };

    // ============================ Phase 1: p1 ============================
    for (int i = tid; i < NBINS; i += TPB) sh_hist[i] = 0;
    if (b == 0 && tid == 0) g_maxbits = 0u;
    __syncthreads();

    int m = b * TPB + tid;    // exact: NBP1*TPB == NMODES
    int L = 0;

    if (b < NBP1) {
        const float PI    = 3.14159265358979323846f;
        const float LX    = 0.5f;
        const float Kf    = 1.0f / 44100.0f;
        const float MAXOM = (float)(20000.0 * M_PI);
        const float MINOM = (float)(40.0 * M_PI);
        const float ALPHA = (float)(3.0 * 2.302585092994045684 / 6.0);
        const float BETA  = (float)(3.0 * 2.302585092994045684
                                    / ((2.0 * M_PI * 500.0) * (2.0 * M_PI * 500.0))
                                    * (1.0 - 1.0 / 6.0));

        float mu = softplusf(mu_raw[0]) + 1e-4f;
        float Dm = softplusf(D_raw[0])  + 1e-4f;
        float T0 = softplusf(T0_raw[0]) + 1e-4f;
        float Ly = 1.1f + (4.0f - 1.1f) * ((tanhf(Ly_raw[0]) + 1.0f) * 0.5f);
        float xo = 0.49f * LX + (1.0f - 0.49f) * LX * ((tanhf(xo_raw[0]) + 1.0f) * 0.5f);
        float yo = 0.51f * Ly + (1.0f - 0.51f) * Ly * ((tanhf(yo_raw[0]) + 1.0f) * 0.5f);
        float xi = 0.1f * LX;
        float yi = 0.1f * Ly;

        float Mf = (float)(m / 80 + 1);
        float Nf = (float)(m % 80 + 1);

        float a1 = Mf * PI / LX;
        float a2 = Nf * PI / Ly;
        float g1 = a1 * a1 + a2 * a2;
        float om2 = T0 * g1 + Dm * g1 * g1;
        float omega = sqrtf(fmaxf(om2, 0.f));
        bool valid = (omega <= MAXOM) && (omega >= MINOM);

        float in_w  = cosf(xi * PI * Mf / LX) * cosf(yi * PI * Nf / Ly);
        float out_w = cosf(xo * PI * Mf / LX) * cosf(yo * PI * Nf / Ly);
        float sigma = ALPHA + BETA * omega * omega;
        float msf   = 0.25f * mu * LX * Ly;
        float theta = omega * Kf;
        float denom = sinf(theta) + 1e-8f;
        float sigK  = sigma * Kf;

        // s[n] = C * r^n * sin(n*theta), r = exp(-sigma*K)
        float Cf = out_w * in_w * (Kf * Kf) / (msf * denom);

        float c1f = 0.f, c2f = 0.f, rinv32f = 0.f, cs32f = 0.f, sn32f = 0.f;
        if (valid) {
            float x  = 32.f * theta;               // exact fp32 product
            float k  = rintf(x * INV2PI);
            float rr = fmaf(-k, P2_0, x);
            rr = fmaf(-k, P2_1, rr);
            rr = fmaf(-k, P2_2, rr);
            float c32 = cosf(rr);
            float s32 = sinf(rr);
            float r32 = expf(-32.f * sigK);
            c1f     = 2.f * r32 * c32;
            c2f     = r32 * r32;
            rinv32f = 1.f / r32;
            cs32f   = c32;
            sn32f   = s32;
            float lc = TLN / (sigK * (float)CHUNK);
            int   Li = (lc >= (float)nchunks) ? nchunks : ((int)lc + 1);
            L = (Li > nchunks) ? nchunks : Li;
            if (L < 1) L = 1;
        }

        g_uA[m] = make_float4(theta, -sigK, c1f, c2f);
        g_uB[m] = make_float4(rinv32f, cs32f, sn32f, valid ? Cf : 0.f);
        g_Lm[m] = L;
        atomicAdd(&sh_hist[L], 1);
    }
    __syncthreads();
    if (b < NBP1)
        for (int i = tid; i < NBINS; i += TPB) g_hist2[i][b] = sh_hist[i];

    grid_barrier();

    // ============================ Phase 2: p3 ============================
    int* wcnt = (int*)shf;                    // [NWARP][NBINS] reuse (8.3KB<16KB)
    if (b < NBP1) {
        for (int i = tid; i < NWARP * NBINS; i += TPB) wcnt[i] = 0;
        for (int i = tid; i < NBINS; i += TPB) {
            int tot = 0, pre = 0;
#pragma unroll
            for (int bb = 0; bb < NBP1; bb++) {
                int h = g_hist2[i][bb];
                tot += h;
                if (bb < b) pre += h;
            }
            offL[i] = tot;
            preB[i] = pre;
        }
        __syncthreads();

        if (tid < 32) {
            // exclusive prefix over DESCENDING lifetime (lane0 = top bin)
            int carry = 0;
#pragma unroll
            for (int seg = 0; seg < (NBINS + 31) / 32; seg++) {
                int Lb  = NBINS - 1 - (seg * 32 + tid);
                int val = (Lb >= 0) ? offL[Lb] : 0;
                int incl = val;
#pragma unroll
                for (int o = 1; o < 32; o <<= 1) {
                    int up = __shfl_up_sync(0xffffffffu, incl, o);
                    if (tid >= o) incl += up;
                }
                if (Lb >= 0) offL[Lb] = carry + (incl - val);
                carry += __shfl_sync(0xffffffffu, incl, 31);
            }
        }

        unsigned mask   = __match_any_sync(0xffffffffu, L);
        int      inwarp = __popc(mask & ((1u << lane) - 1u));
        int      leader = __ffs(mask) - 1;
        if (lane == leader) wcnt[wid * NBINS + L] = __popc(mask);
        __syncthreads();

        if (b == 0)
            for (int c = tid; c < nchunks; c += TPB) g_cnt[c] = offL[c];

        int local = inwarp;
#pragma unroll
        for (int w2 = 0; w2 < NWARP; w2++)
            if (w2 < wid) local += wcnt[w2 * NBINS + L];
        int rank = offL[L] + preB[L] + local;
        g_pA[rank] = g_uA[m];
        g_pB[rank] = g_uB[m];
    }

    grid_barrier();

    // ========================== Phase 3: modal ==========================
    // Logical block LB -> chunk c = LB/8, octet q = LB%8; warp -> group
    // g = q*8 + wid. Two independent stride-64 recurrences, exact seeds via
    // float Dekker + Cody-Waite; fixed-order smem combine -> buffer q.
    {
        const float lf = (float)lane;
        int LBtot = nchunks * GR;
        for (int LB = b; LB < LBtot; LB += NBLK) {
            int c  = LB >> 3;
            int q  = LB & 7;
            int g  = q * NWARP + wid;
            int n0 = c * CHUNK;
            float n0f = (float)n0;

            int cnt  = g_cnt[c];
            int base = (cnt * g) >> 6;        // G == 64
            int end  = (cnt * (g + 1)) >> 6;

            float acc[U];
#pragma unroll
            for (int j = 0; j < U; j++) acc[j] = 0.f;

            for (int r = base; r < end; ++r) {
                float4 pa = g_pA[r];
                float4 pb = g_pB[r];
                float theta = pa.x, msigK = pa.y, c1 = pa.z, c2 = pa.w;
                float rinv32 = pb.x, cs32 = pb.y, sn32 = pb.z, C = pb.w;

                // chunk phase: exact product + 3-term Cody-Waite reduction
                float p  = n0f * theta;
                float e  = fmaf(n0f, theta, -p);
                float k  = rintf(p * INV2PI);
                float rr = fmaf(-k, P2_0, p);
                rr = fmaf(-k, P2_1, rr);
                rr = fmaf(-k, P2_2, rr);
                float psi = rr + e;

                float a  = fmaf(lf, theta, psi);
                float k2 = rintf(a * INV2PI);
                a = fmaf(-k2, P2_0, a);
                a = fmaf(-k2, P2_1, a);
                float s, co;
                __sincosf(a, &s, &co);
                float Ae = C * __expf(msigK * (n0f + lf));

                float cs64   = fmaf(2.f * cs32, cs32, -1.f);
                float sn64   = 2.f * sn32 * cs32;
                float rinv64 = rinv32 * rinv32;

                float cur0  = Ae * s;                                     // s[n]
                float prev1 = (Ae * rinv32) * fmaf(s, cs32, -co * sn32);  // s[n-32]
                float prev0 = (Ae * rinv64) * fmaf(s, cs64, -co * sn64);  // s[n-64]
                float cur1  = fmaf(c1, cur0, -(c2 * prev1));              // s[n+32]

                float c1q = fmaf(c1, c1, -(c2 + c2));
                float c2q = c2 * c2;

#pragma unroll
                for (int jj = 0; jj < U / 2; jj++) {
                    acc[2 * jj]     += cur0;
                    acc[2 * jj + 1] += cur1;
                    float n0x = fmaf(c1q, cur0, -(c2q * prev0));
                    float n1x = fmaf(c1q, cur1, -(c2q * prev1));
                    prev0 = cur0; cur0 = n0x;
                    prev1 = cur1; cur1 = n1x;
                }
            }

            __syncthreads();   // shf free (previous combine / p3 reuse done)
#pragma unroll
            for (int j = 0; j < U; j++)
                shf[wid][j * 32 + lane] = acc[j];
            __syncthreads();

            // fixed-order combine (group ascending) -> one buffer per octet
            float* dst = g_partial + (size_t)q * MAX_SAMPLES;
#pragma unroll
            for (int t = 0; t < 2; t++) {
                int s = tid + t * TPB;
                float v = ((shf[0][s] + shf[1][s]) + (shf[2][s] + shf[3][s]))
                        + ((shf[4][s] + shf[5][s]) + (shf[6][s] + shf[7][s]));
                int n = n0 + s;
                if (n < N) dst[n] = v;
            }
        }
    }

    grid_barrier();

    // ===================== Phase 4: reduce + normalize ===================
    {
        int n = b * TPB + tid;    // NBLK*TPB = 151552 >= MAX_SAMPLES
        float v = 0.f;
        if (n < N) {
#pragma unroll
            for (int g = 0; g < GR; g++)
                v += __ldcg(&g_partial[(size_t)g * MAX_SAMPLES + n]);
        }

        float am = (n < N) ? fabsf(v) : 0.f;
#pragma unroll
        for (int o = 16; o; o >>= 1)
            am = fmaxf(am, __shfl_xor_sync(0xffffffffu, am, o));
        if (lane == 0) wmax[wid] = am;
        __syncthreads();
        if (tid == 0) {
            float bm = wmax[0];
#pragma unroll
            for (int i = 1; i < NWARP; i++) bm = fmaxf(bm, wmax[i]);
            atomicMax(&g_maxbits, __float_as_uint(bm));  // order-independent
        }

        grid_barrier();

        float inv = 1.0f / (__uint_as_float(__ldcg(&g_maxbits)) + 1e-8f);
        if (n < N) out[n] = v * inv;
    }
}

// ---------------------------------------------------------------------------
extern "C" void kernel_launch(void* const* d_in, const int* in_sizes, int n_in,
                              void* d_out, int out_size)
{
    const float* mu_raw = (const float*)d_in[0];
    const float* D_raw  = (const float*)d_in[1];
    const float* T0_raw = (const float*)d_in[2];
    const float* Ly_raw = (const float*)d_in[3];
    const float* xo_raw = (const float*)d_in[4];
    const float* yo_raw = (const float*)d_in[5];

    int N = out_size;
    if (N > MAX_SAMPLES) N = MAX_SAMPLES;
    int nchunks = (N + CHUNK - 1) / CHUNK;

    mega_kernel<<<NBLK, TPB>>>(mu_raw, D_raw, T0_raw, Ly_raw, xo_raw, yo_raw,
                               (float*)d_out, N, nchunks);
}

// round 16
// speedup vs baseline: 1.2000x; 1.2000x over previous
#include <cuda_runtime.h>
#include <math.h>

#define NMODES      6400
#define TPB         256           // threads per block (8 warps)
#define NBLK        592           // 4 blocks/SM * 148 SMs -> wave-1 co-resident
#define NBP1        25            // blocks that own modes (25*256 = 6400)
#define NWARP       8
#define NCNT        8             // distributed barrier counters
#define BPC         (NBLK / NCNT) // blocks per counter = 74
#define NBINS       260           // lifetime bins (0..258)
#define CHUNK       512           // samples per warp-chunk = 32 lanes * U
#define U           16            // accumulators per lane
#define G           64            // mode groups (warp granularity)
#define GR          8             // partial buffers (one per 8-group octet)
#define MAX_SAMPLES 132096
#define MAX_CHUNKS  258
#define TLN         18.0f         // -ln(~1.5e-8) relative amplitude cutoff

// Static scratch (no runtime allocation allowed)
__device__ float4       g_uA[NMODES], g_uB[NMODES];   // unsorted per-mode params
__device__ int          g_Lm[NMODES];                 // lifetime in chunks
__device__ int          g_hist2[NBINS][NBP1];
__device__ int          g_cnt[MAX_CHUNKS];            // #active modes at chunk c
__device__ float4       g_pA[NMODES], g_pB[NMODES];   // lifetime-sorted params
__device__ float        g_partial[(size_t)GR * MAX_SAMPLES];
__device__ unsigned int g_maxbits;
__device__ unsigned int g_work;                       // dynamic modal work queue
__device__ volatile unsigned int g_ctr[NCNT];         // barrier counters (monotonic)

__device__ __forceinline__ float softplusf(float x) {
    return (x > 20.f) ? x : log1pf(expf(x));
}

// 2pi split for Cody-Waite (compile-time constants)
#define INV2PI 0.15915494309189535f
#define P2_0   6.28125f
#define P2_1   ((float)(6.283185307179586476925 - 6.28125))
#define P2_2   ((float)(6.283185307179586476925 - 6.28125 \
                        - (double)(float)(6.283185307179586476925 - 6.28125)))

// ---------------------------------------------------------------------------
// Megakernel v3: p1 -> p3 -> modal (DYNAMIC work queue) -> reduce+norm.
// ---------------------------------------------------------------------------
__global__ void __launch_bounds__(TPB, 4) mega_kernel(
    const float* mu_raw, const float* D_raw, const float* T0_raw,
    const float* Ly_raw, const float* xo_raw, const float* yo_raw,
    float* out, int N, int nchunks)
{
    __shared__ float shf[NWARP][CHUNK];   // 16 KB: modal combine / p3 wcnt
    __shared__ int   offL[NBINS];
    __shared__ int   preB[NBINS];
    __shared__ int   sh_hist[NBINS];
    __shared__ float wmax[NWARP];
    __shared__ unsigned int sh_tgt;
    __shared__ int   sh_lb;

    const int tid  = threadIdx.x;
    const int b    = blockIdx.x;
    const int wid  = tid >> 5;
    const int lane = tid & 31;

    // Distributed grid barrier (validated R14/R15). Barrier instances are
    // globally serialized, so (old/BPC+1)*BPC is the instance target for ALL
    // counters; monotonic across graph replays.
    auto grid_barrier = [&]() {
        __threadfence();
        __syncthreads();
        if (tid == 0) {
            unsigned int old = atomicAdd((unsigned int*)&g_ctr[b & (NCNT - 1)], 1u);
            sh_tgt = (old / BPC + 1u) * BPC;
        }
        __syncthreads();
        if (tid < NCNT) {
            unsigned int t = sh_tgt;
            while (g_ctr[tid] < t) { }
        }
        __syncthreads();
        __threadfence();   // acquire: order peer data after observed arrivals
    };

    // ============================ Phase 1: p1 ============================
    for (int i = tid; i < NBINS; i += TPB) sh_hist[i] = 0;
    if (b == 0 && tid == 0) { g_maxbits = 0u; g_work = 0u; }
    __syncthreads();

    int m = b * TPB + tid;    // exact: NBP1*TPB == NMODES
    int L = 0;

    if (b < NBP1) {
        const float PI    = 3.14159265358979323846f;
        const float LX    = 0.5f;
        const float Kf    = 1.0f / 44100.0f;
        const float MAXOM = (float)(20000.0 * M_PI);
        const float MINOM = (float)(40.0 * M_PI);
        const float ALPHA = (float)(3.0 * 2.302585092994045684 / 6.0);
        const float BETA  = (float)(3.0 * 2.302585092994045684
                                    / ((2.0 * M_PI * 500.0) * (2.0 * M_PI * 500.0))
                                    * (1.0 - 1.0 / 6.0));

        float mu = softplusf(mu_raw[0]) + 1e-4f;
        float Dm = softplusf(D_raw[0])  + 1e-4f;
        float T0 = softplusf(T0_raw[0]) + 1e-4f;
        float Ly = 1.1f + (4.0f - 1.1f) * ((tanhf(Ly_raw[0]) + 1.0f) * 0.5f);
        float xo = 0.49f * LX + (1.0f - 0.49f) * LX * ((tanhf(xo_raw[0]) + 1.0f) * 0.5f);
        float yo = 0.51f * Ly + (1.0f - 0.51f) * Ly * ((tanhf(yo_raw[0]) + 1.0f) * 0.5f);
        float xi = 0.1f * LX;
        float yi = 0.1f * Ly;

        float Mf = (float)(m / 80 + 1);
        float Nf = (float)(m % 80 + 1);

        float a1 = Mf * PI / LX;
        float a2 = Nf * PI / Ly;
        float g1 = a1 * a1 + a2 * a2;
        float om2 = T0 * g1 + Dm * g1 * g1;
        float omega = sqrtf(fmaxf(om2, 0.f));
        bool valid = (omega <= MAXOM) && (omega >= MINOM);

        float in_w  = cosf(xi * PI * Mf / LX) * cosf(yi * PI * Nf / Ly);
        float out_w = cosf(xo * PI * Mf / LX) * cosf(yo * PI * Nf / Ly);
        float sigma = ALPHA + BETA * omega * omega;
        float msf   = 0.25f * mu * LX * Ly;
        float theta = omega * Kf;
        float denom = sinf(theta) + 1e-8f;
        float sigK  = sigma * Kf;

        // s[n] = C * r^n * sin(n*theta), r = exp(-sigma*K)
        float Cf = out_w * in_w * (Kf * Kf) / (msf * denom);

        float c1f = 0.f, c2f = 0.f, rinv32f = 0.f, cs32f = 0.f, sn32f = 0.f;
        if (valid) {
            float x  = 32.f * theta;               // exact fp32 product
            float k  = rintf(x * INV2PI);
            float rr = fmaf(-k, P2_0, x);
            rr = fmaf(-k, P2_1, rr);
            rr = fmaf(-k, P2_2, rr);
            float c32 = cosf(rr);
            float s32 = sinf(rr);
            float r32 = expf(-32.f * sigK);
            c1f     = 2.f * r32 * c32;
            c2f     = r32 * r32;
            rinv32f = 1.f / r32;
            cs32f   = c32;
            sn32f   = s32;
            float lc = TLN / (sigK * (float)CHUNK);
            int   Li = (lc >= (float)nchunks) ? nchunks : ((int)lc + 1);
            L = (Li > nchunks) ? nchunks : Li;
            if (L < 1) L = 1;
        }

        g_uA[m] = make_float4(theta, -sigK, c1f, c2f);
        g_uB[m] = make_float4(rinv32f, cs32f, sn32f, valid ? Cf : 0.f);
        g_Lm[m] = L;
        atomicAdd(&sh_hist[L], 1);
    }
    __syncthreads();
    if (b < NBP1)
        for (int i = tid; i < NBINS; i += TPB) g_hist2[i][b] = sh_hist[i];

    grid_barrier();

    // ============================ Phase 2: p3 ============================
    int* wcnt = (int*)shf;                    // [NWARP][NBINS] reuse
    if (b < NBP1) {
        for (int i = tid; i < NWARP * NBINS; i += TPB) wcnt[i] = 0;
        for (int i = tid; i < NBINS; i += TPB) {
            int tot = 0, pre = 0;
#pragma unroll
            for (int bb = 0; bb < NBP1; bb++) {
                int h = g_hist2[i][bb];
                tot += h;
                if (bb < b) pre += h;
            }
            offL[i] = tot;
            preB[i] = pre;
        }
        __syncthreads();

        if (tid < 32) {
            // exclusive prefix over DESCENDING lifetime (lane0 = top bin)
            int carry = 0;
#pragma unroll
            for (int seg = 0; seg < (NBINS + 31) / 32; seg++) {
                int Lb  = NBINS - 1 - (seg * 32 + tid);
                int val = (Lb >= 0) ? offL[Lb] : 0;
                int incl = val;
#pragma unroll
                for (int o = 1; o < 32; o <<= 1) {
                    int up = __shfl_up_sync(0xffffffffu, incl, o);
                    if (tid >= o) incl += up;
                }
                if (Lb >= 0) offL[Lb] = carry + (incl - val);
                carry += __shfl_sync(0xffffffffu, incl, 31);
            }
        }

        unsigned mask   = __match_any_sync(0xffffffffu, L);
        int      inwarp = __popc(mask & ((1u << lane) - 1u));
        int      leader = __ffs(mask) - 1;
        if (lane == leader) wcnt[wid * NBINS + L] = __popc(mask);
        __syncthreads();

        if (b == 0)
            for (int c = tid; c < nchunks; c += TPB) g_cnt[c] = offL[c];

        int local = inwarp;
#pragma unroll
        for (int w2 = 0; w2 < NWARP; w2++)
            if (w2 < wid) local += wcnt[w2 * NBINS + L];
        int rank = offL[L] + preB[L] + local;
        g_pA[rank] = g_uA[m];
        g_pB[rank] = g_uB[m];
    }

    grid_barrier();

    // ========================== Phase 3: modal ==========================
    // DYNAMIC queue: blocks grab logical blocks (LB -> chunk c=LB/8, octet
    // q=LB%8) in heavy-first order via atomicAdd — reproduces the HW
    // scheduler's load balancing that the static stride destroyed (R14/R15).
    {
        const float lf = (float)lane;
        const int LBtot = nchunks * GR;
        for (;;) {
            if (tid == 0) sh_lb = (int)atomicAdd(&g_work, 1u);
            __syncthreads();
            int LB = sh_lb;
            if (LB >= LBtot) break;

            int c  = LB >> 3;
            int q  = LB & 7;
            int g  = q * NWARP + wid;
            int n0 = c * CHUNK;
            float n0f = (float)n0;

            int cnt  = g_cnt[c];
            int base = (cnt * g) >> 6;        // G == 64
            int end  = (cnt * (g + 1)) >> 6;

            float acc[U];
#pragma unroll
            for (int j = 0; j < U; j++) acc[j] = 0.f;

            for (int r = base; r < end; ++r) {
                float4 pa = g_pA[r];
                float4 pb = g_pB[r];
                float theta = pa.x, msigK = pa.y, c1 = pa.z, c2 = pa.w;
                float rinv32 = pb.x, cs32 = pb.y, sn32 = pb.z, C = pb.w;

                // chunk phase: exact product + 3-term Cody-Waite reduction
                float p  = n0f * theta;
                float e  = fmaf(n0f, theta, -p);
                float k  = rintf(p * INV2PI);
                float rr = fmaf(-k, P2_0, p);
                rr = fmaf(-k, P2_1, rr);
                rr = fmaf(-k, P2_2, rr);
                float psi = rr + e;

                float a  = fmaf(lf, theta, psi);
                float k2 = rintf(a * INV2PI);
                a = fmaf(-k2, P2_0, a);
                a = fmaf(-k2, P2_1, a);
                float s, co;
                __sincosf(a, &s, &co);
                float Ae = C * __expf(msigK * (n0f + lf));

                float cs64   = fmaf(2.f * cs32, cs32, -1.f);
                float sn64   = 2.f * sn32 * cs32;
                float rinv64 = rinv32 * rinv32;

                float cur0  = Ae * s;                                     // s[n]
                float prev1 = (Ae * rinv32) * fmaf(s, cs32, -co * sn32);  // s[n-32]
                float prev0 = (Ae * rinv64) * fmaf(s, cs64, -co * sn64);  // s[n-64]
                float cur1  = fmaf(c1, cur0, -(c2 * prev1));              // s[n+32]

                float c1q = fmaf(c1, c1, -(c2 + c2));
                float c2q = c2 * c2;

#pragma unroll
                for (int jj = 0; jj < U / 2; jj++) {
                    acc[2 * jj]     += cur0;
                    acc[2 * jj + 1] += cur1;
                    float n0x = fmaf(c1q, cur0, -(c2q * prev0));
                    float n1x = fmaf(c1q, cur1, -(c2q * prev1));
                    prev0 = cur0; cur0 = n0x;
                    prev1 = cur1; cur1 = n1x;
                }
            }

            __syncthreads();   // shf free (prev combine done / p3 reuse done)
#pragma unroll
            for (int j = 0; j < U; j++)
                shf[wid][j * 32 + lane] = acc[j];
            __syncthreads();

            // fixed-order combine (group ascending) -> one buffer per octet
            float* dst = g_partial + (size_t)q * MAX_SAMPLES;
#pragma unroll
            for (int t = 0; t < 2; t++) {
                int s = tid + t * TPB;
                float v = ((shf[0][s] + shf[1][s]) + (shf[2][s] + shf[3][s]))
                        + ((shf[4][s] + shf[5][s]) + (shf[6][s] + shf[7][s]));
                int n = n0 + s;
                if (n < N) dst[n] = v;
            }
            __syncthreads();   // all threads done with sh_lb & shf before regrab
        }
    }

    grid_barrier();

    // ===================== Phase 4: reduce + normalize ===================
    {
        int n = b * TPB + tid;    // NBLK*TPB = 151552 >= MAX_SAMPLES
        float v = 0.f;
        if (n < N) {
#pragma unroll
            for (int g = 0; g < GR; g++)
                v += __ldcg(&g_partial[(size_t)g * MAX_SAMPLES + n]);
        }

        float am = (n < N) ? fabsf(v) : 0.f;
#pragma unroll
        for (int o = 16; o; o >>= 1)
            am = fmaxf(am, __shfl_xor_sync(0xffffffffu, am, o));
        if (lane == 0) wmax[wid] = am;
        __syncthreads();
        if (tid == 0) {
            float bm = wmax[0];
#pragma unroll
            for (int i = 1; i < NWARP; i++) bm = fmaxf(bm, wmax[i]);
            atomicMax(&g_maxbits, __float_as_uint(bm));  // order-independent
        }

        grid_barrier();

        float inv = 1.0f / (__uint_as_float(__ldcg(&g_maxbits)) + 1e-8f);
        if (n < N) out[n] = v * inv;
    }
}

// ---------------------------------------------------------------------------
extern "C" void kernel_launch(void* const* d_in, const int* in_sizes, int n_in,
                              void* d_out, int out_size)
{
    const float* mu_raw = (const float*)d_in[0];
    const float* D_raw  = (const float*)d_in[1];
    const float* T0_raw = (const float*)d_in[2];
    const float* Ly_raw = (const float*)d_in[3];
    const float* xo_raw = (const float*)d_in[4];
    const float* yo_raw = (const float*)d_in[5];

    int N = out_size;
    if (N > MAX_SAMPLES) N = MAX_SAMPLES;
    int nchunks = (N + CHUNK - 1) / CHUNK;

    mega_kernel<<<NBLK, TPB>>>(mu_raw, D_raw, T0_raw, Ly_raw, xo_raw, yo_raw,
                               (float*)d_out, N, nchunks);
}

// round 17
// speedup vs baseline: 1.4212x; 1.1843x over previous
#include <cuda_runtime.h>
#include <math.h>

#define NMODES      6400
#define NB          50            // p13 blocks (co-resident: 50 <= 148)
#define TPB         128           // threads per block in p13 (NB*TPB = NMODES)
#define NWARP       (TPB / 32)
#define NBINS       260           // lifetime bins (0..258)
#define CHUNK       512           // samples per warp-chunk = 32 lanes * U
#define U           16            // accumulators per lane
#define G           64            // mode groups (warp granularity)
#define GR          8             // partial buffers (one per 8-group octet)
#define MAX_SAMPLES 132096
#define MAX_CHUNKS  258
#define TLN         18.0f         // -ln(~1.5e-8) relative amplitude cutoff
#define RB          148           // reduce blocks: 1/SM, co-resident

// Static scratch (no runtime allocation allowed)
__device__ int          g_hist2[NBINS][NB];
__device__ int          g_cnt[MAX_CHUNKS];            // #active modes at chunk c
__device__ float4       g_pA[NMODES], g_pB[NMODES];   // lifetime-sorted params
__device__ float        g_partial[(size_t)GR * MAX_SAMPLES];
__device__ unsigned int g_maxbits;
__device__ unsigned int g_bar1 = 0u;                  // p13 barrier (monotonic)
__device__ unsigned int g_bar2 = 0u;                  // reduce barrier (monotonic)

__device__ __forceinline__ float softplusf(float x) {
    return (x > 20.f) ? x : log1pf(expf(x));
}

// 2pi split for Cody-Waite (compile-time constants)
#define INV2PI 0.15915494309189535f
#define P2_0   6.28125f
#define P2_1   ((float)(6.283185307179586476925 - 6.28125))
#define P2_2   ((float)(6.283185307179586476925 - 6.28125 \
                        - (double)(float)(6.283185307179586476925 - 6.28125)))

// ---------------------------------------------------------------------------
// P13: params (phase A) + barrier + sort-scatter (phase B). 50 x 128.
// All 50 blocks co-resident (1 wave) => spin barrier is deadlock-free.
// Params stay in REGISTERS across the barrier (no g_uA/g_uB round trip).
// Sort: descending lifetime, ascending block, original order within block.
// ---------------------------------------------------------------------------
__global__ void __launch_bounds__(TPB) p13_kernel(
    const float* mu_raw, const float* D_raw, const float* T0_raw,
    const float* Ly_raw, const float* xo_raw, const float* yo_raw, int nchunks)
{
    __shared__ int sh_hist[NBINS];
    __shared__ int offL[NBINS];          // totals, then exclusive-desc prefix
    __shared__ int preB[NBINS];          // contribution of blocks < b in bin
    __shared__ int wcnt[NWARP][NBINS];   // per-warp per-bin counts

    const int tid  = threadIdx.x;
    const int b    = blockIdx.x;
    const int wid  = tid >> 5;
    const int lane = tid & 31;

    // ---------------- Phase A: per-mode params + histogram ----------------
    for (int i = tid; i < NBINS; i += TPB) sh_hist[i] = 0;
    if (b == 0 && tid == 0) g_maxbits = 0u;
    __syncthreads();

    const int m = b * TPB + tid;         // exact: NB*TPB == NMODES

    const float PI    = 3.14159265358979323846f;
    const float LX    = 0.5f;
    const float Kf    = 1.0f / 44100.0f;
    const float MAXOM = (float)(20000.0 * M_PI);
    const float MINOM = (float)(40.0 * M_PI);
    const float ALPHA = (float)(3.0 * 2.302585092994045684 / 6.0);
    const float BETA  = (float)(3.0 * 2.302585092994045684
                                / ((2.0 * M_PI * 500.0) * (2.0 * M_PI * 500.0))
                                * (1.0 - 1.0 / 6.0));

    float mu = softplusf(mu_raw[0]) + 1e-4f;
    float Dm = softplusf(D_raw[0])  + 1e-4f;
    float T0 = softplusf(T0_raw[0]) + 1e-4f;
    float Ly = 1.1f + (4.0f - 1.1f) * ((tanhf(Ly_raw[0]) + 1.0f) * 0.5f);
    float xo = 0.49f * LX + (1.0f - 0.49f) * LX * ((tanhf(xo_raw[0]) + 1.0f) * 0.5f);
    float yo = 0.51f * Ly + (1.0f - 0.51f) * Ly * ((tanhf(yo_raw[0]) + 1.0f) * 0.5f);
    float xi = 0.1f * LX;
    float yi = 0.1f * Ly;

    float Mf = (float)(m / 80 + 1);
    float Nf = (float)(m % 80 + 1);

    float a1 = Mf * PI / LX;
    float a2 = Nf * PI / Ly;
    float g1 = a1 * a1 + a2 * a2;
    float om2 = T0 * g1 + Dm * g1 * g1;
    float omega = sqrtf(fmaxf(om2, 0.f));
    bool valid = (omega <= MAXOM) && (omega >= MINOM);

    float in_w  = cosf(xi * PI * Mf / LX) * cosf(yi * PI * Nf / Ly);
    float out_w = cosf(xo * PI * Mf / LX) * cosf(yo * PI * Nf / Ly);
    float sigma = ALPHA + BETA * omega * omega;
    float msf   = 0.25f * mu * LX * Ly;
    float theta = omega * Kf;
    float denom = sinf(theta) + 1e-8f;
    float sigK  = sigma * Kf;

    // s[n] = C * r^n * sin(n*theta), r = exp(-sigma*K)
    float Cf = out_w * in_w * (Kf * Kf) / (msf * denom);

    int L = 0;
    float c1f = 0.f, c2f = 0.f, rinv32f = 0.f, cs32f = 0.f, sn32f = 0.f;
    if (valid) {
        float x  = 32.f * theta;               // exact fp32 product
        float k  = rintf(x * INV2PI);
        float rr = fmaf(-k, P2_0, x);
        rr = fmaf(-k, P2_1, rr);
        rr = fmaf(-k, P2_2, rr);
        float c32 = cosf(rr);
        float s32 = sinf(rr);
        float r32 = expf(-32.f * sigK);
        c1f     = 2.f * r32 * c32;
        c2f     = r32 * r32;
        rinv32f = 1.f / r32;
        cs32f   = c32;
        sn32f   = s32;
        float lc = TLN / (sigK * (float)CHUNK);
        int   Li = (lc >= (float)nchunks) ? nchunks : ((int)lc + 1);
        L = (Li > nchunks) ? nchunks : Li;
        if (L < 1) L = 1;
    }
    // params kept in registers: uA = (theta, -sigK, c1f, c2f),
    //                           uB = (rinv32f, cs32f, sn32f, valid?Cf:0)
    float4 uA = make_float4(theta, -sigK, c1f, c2f);
    float4 uB = make_float4(rinv32f, cs32f, sn32f, valid ? Cf : 0.f);

    atomicAdd(&sh_hist[L], 1);
    __syncthreads();
    for (int i = tid; i < NBINS; i += TPB) g_hist2[i][b] = sh_hist[i];

    // ---- grid barrier: all 50 blocks' histograms visible ----
    __threadfence();
    __syncthreads();
    if (tid == 0) {
        unsigned int old = atomicAdd(&g_bar1, 1u);
        unsigned int target = old - (old % NB) + NB;   // monotonic across replays
        while (*(volatile unsigned int*)&g_bar1 < target) { }
    }
    __syncthreads();
    __threadfence();

    // ---------------- Phase B: offsets + deterministic scatter ------------
    for (int i = tid; i < NWARP * NBINS; i += TPB) ((int*)wcnt)[i] = 0;

    for (int i = tid; i < NBINS; i += TPB) {
        int tot = 0, pre = 0;
#pragma unroll
        for (int bb = 0; bb < NB; bb++) {
            int h = g_hist2[i][bb];
            tot += h;
            if (bb < b) pre += h;
        }
        offL[i] = tot;
        preB[i] = pre;
    }
    __syncthreads();

    // exclusive prefix over DESCENDING lifetime, via warp scan (lane0 = top)
    if (tid < 32) {
        int carry = 0;
#pragma unroll
        for (int seg = 0; seg < (NBINS + 31) / 32; seg++) {
            int Lb  = NBINS - 1 - (seg * 32 + tid);
            int val = (Lb >= 0) ? offL[Lb] : 0;
            int incl = val;
#pragma unroll
            for (int o = 1; o < 32; o <<= 1) {
                int up = __shfl_up_sync(0xffffffffu, incl, o);
                if (tid >= o) incl += up;
            }
            if (Lb >= 0) offL[Lb] = carry + (incl - val);
            carry += __shfl_sync(0xffffffffu, incl, 31);
        }
    }

    unsigned mask   = __match_any_sync(0xffffffffu, L);
    int      inwarp = __popc(mask & ((1u << lane) - 1u));
    int      leader = __ffs(mask) - 1;
    if (lane == leader) wcnt[wid][L] = __popc(mask);
    __syncthreads();

    if (b == 0)
        for (int c = tid; c < nchunks; c += TPB) g_cnt[c] = offL[c];

    int local = inwarp;
#pragma unroll
    for (int w2 = 0; w2 < NWARP; w2++)
        if (w2 < wid) local += wcnt[w2][L];
    int rank = offL[L] + preB[L] + local;
    g_pA[rank] = uA;
    g_pB[rank] = uB;
}

// ---------------------------------------------------------------------------
// Modal synthesis (R11-validated). Block = 8 warps = 8 consecutive groups of
// ONE chunk: block B -> chunk c = B/8, octet q = B%8, warp wid -> g = q*8+wid.
// Two independent stride-64 recurrences per mode; exact seeds via float
// Dekker + Cody-Waite; fixed-order smem combine -> one buffer per octet.
// ---------------------------------------------------------------------------
__global__ void __launch_bounds__(256) modal_kernel(int N, int nchunks)
{
    __shared__ float sh[8][CHUNK];   // 16 KB

    int B    = blockIdx.x;
    int wid  = threadIdx.x >> 5;
    int lane = threadIdx.x & 31;
    int c  = B >> 3;                 // 8 blocks per chunk
    int q  = B & 7;                  // octet
    int g  = q * 8 + wid;
    int n0 = c * CHUNK;

    int cnt  = g_cnt[c];
    int base = (cnt * g) >> 6;       // G == 64
    int end  = (cnt * (g + 1)) >> 6;

    float acc[U];
#pragma unroll
    for (int j = 0; j < U; j++) acc[j] = 0.f;

    float lf  = (float)lane;
    float n0f = (float)n0;

    for (int r = base; r < end; ++r) {
        float4 pa = g_pA[r];
        float4 pb = g_pB[r];
        float theta = pa.x, msigK = pa.y, c1 = pa.z, c2 = pa.w;
        float rinv32 = pb.x, cs32 = pb.y, sn32 = pb.z, C = pb.w;

        // chunk phase: (n0 * theta) mod 2pi, exact product + 3-term reduction
        float p  = n0f * theta;
        float e  = fmaf(n0f, theta, -p);
        float k  = rintf(p * INV2PI);
        float rr = fmaf(-k, P2_0, p);
        rr = fmaf(-k, P2_1, rr);
        rr = fmaf(-k, P2_2, rr);
        float psi = rr + e;

        // per-lane phase and amplitude
        float a  = fmaf(lf, theta, psi);
        float k2 = rintf(a * INV2PI);
        a = fmaf(-k2, P2_0, a);
        a = fmaf(-k2, P2_1, a);
        float s, co;
        __sincosf(a, &s, &co);
        float Ae = C * __expf(msigK * (n0f + lf));

        // rotation terms for -32 and -64 steps
        float cs64   = fmaf(2.f * cs32, cs32, -1.f);   // cos(64*theta)
        float sn64   = 2.f * sn32 * cs32;              // sin(64*theta)
        float rinv64 = rinv32 * rinv32;

        float cur0  = Ae * s;                                      // s[n]
        float prev1 = (Ae * rinv32) * fmaf(s, cs32, -co * sn32);   // s[n-32]
        float prev0 = (Ae * rinv64) * fmaf(s, cs64, -co * sn64);   // s[n-64]
        float cur1  = fmaf(c1, cur0, -(c2 * prev1));               // s[n+32]

        // stride-64 coefficients: 2 r^64 cos(64th) = c1^2 - 2 c2 ; r^128 = c2^2
        float c1q = fmaf(c1, c1, -(c2 + c2));
        float c2q = c2 * c2;

#pragma unroll
        for (int jj = 0; jj < U / 2; jj++) {
            acc[2 * jj]     += cur0;
            acc[2 * jj + 1] += cur1;
            float n0x = fmaf(c1q, cur0, -(c2q * prev0));
            float n1x = fmaf(c1q, cur1, -(c2q * prev1));
            prev0 = cur0; cur0 = n0x;
            prev1 = cur1; cur1 = n1x;
        }
    }

    // stage per-warp results in smem
#pragma unroll
    for (int j = 0; j < U; j++)
        sh[wid][j * 32 + lane] = acc[j];
    __syncthreads();

    // fixed-order combine (wid 0..7 == group ascending) -> one buffer per octet
    int tid = threadIdx.x;
    float* dst = g_partial + (size_t)q * MAX_SAMPLES;
#pragma unroll
    for (int t = 0; t < 2; t++) {
        int s = tid + t * 256;
        float v = ((sh[0][s] + sh[1][s]) + (sh[2][s] + sh[3][s]))
                + ((sh[4][s] + sh[5][s]) + (sh[6][s] + sh[7][s]));
        int n = n0 + s;
        if (n < N) dst[n] = v;
    }
}

// ---------------------------------------------------------------------------
// Fused reduce + normalize (R11-validated). 148 co-resident blocks; sums in
// NAMED registers; peak via atomicMax on float bits (order-independent).
// ---------------------------------------------------------------------------
__global__ void __launch_bounds__(256) reduce_norm_kernel(float* out, int N)
{
    const int stride = RB * 256;
    int t0 = blockIdx.x * 256 + threadIdx.x;
    int n1 = t0 + stride, n2 = t0 + 2 * stride, n3 = t0 + 3 * stride;

    float v0 = 0.f, v1 = 0.f, v2 = 0.f, v3 = 0.f;
    if (t0 < N) {
#pragma unroll
        for (int g = 0; g < GR; g++) v0 += g_partial[(size_t)g * MAX_SAMPLES + t0];
    }
    if (n1 < N) {
#pragma unroll
        for (int g = 0; g < GR; g++) v1 += g_partial[(size_t)g * MAX_SAMPLES + n1];
    }
    if (n2 < N) {
#pragma unroll
        for (int g = 0; g < GR; g++) v2 += g_partial[(size_t)g * MAX_SAMPLES + n2];
    }
    if (n3 < N) {
#pragma unroll
        for (int g = 0; g < GR; g++) v3 += g_partial[(size_t)g * MAX_SAMPLES + n3];
    }

    float am = fmaxf(fmaxf(fabsf(v0), fabsf(v1)), fmaxf(fabsf(v2), fabsf(v3)));
#pragma unroll
    for (int o = 16; o; o >>= 1)
        am = fmaxf(am, __shfl_xor_sync(0xffffffffu, am, o));
    __shared__ float wmax[8];
    int wr = threadIdx.x >> 5;
    if ((threadIdx.x & 31) == 0) wmax[wr] = am;
    __syncthreads();

    if (threadIdx.x == 0) {
        float bm = wmax[0];
#pragma unroll
        for (int i = 1; i < 8; i++) bm = fmaxf(bm, wmax[i]);
        atomicMax(&g_maxbits, __float_as_uint(bm));
        __threadfence();   // order atomicMax before counter arrival
        unsigned int old = atomicAdd(&g_bar2, 1u);
        unsigned int target = old - (old % RB) + RB;   // monotonic across replays
        while (*(volatile unsigned int*)&g_bar2 < target) { }
    }
    __syncthreads();

    float inv = 1.0f / (__uint_as_float(__ldcg(&g_maxbits)) + 1e-8f);
    if (t0 < N) out[t0] = v0 * inv;
    if (n1 < N) out[n1] = v1 * inv;
    if (n2 < N) out[n2] = v2 * inv;
    if (n3 < N) out[n3] = v3 * inv;
}

// ---------------------------------------------------------------------------
extern "C" void kernel_launch(void* const* d_in, const int* in_sizes, int n_in,
                              void* d_out, int out_size)
{
    const float* mu_raw = (const float*)d_in[0];
    const float* D_raw  = (const float*)d_in[1];
    const float* T0_raw = (const float*)d_in[2];
    const float* Ly_raw = (const float*)d_in[3];
    const float* xo_raw = (const float*)d_in[4];
    const float* yo_raw = (const float*)d_in[5];

    int N = out_size;
    if (N > MAX_SAMPLES) N = MAX_SAMPLES;
    int nchunks = (N + CHUNK - 1) / CHUNK;

    p13_kernel<<<NB, TPB>>>(mu_raw, D_raw, T0_raw, Ly_raw, xo_raw, yo_raw, nchunks);

    int blocks = nchunks * (G / 8);       // 8 warps (one octet) per block
    modal_kernel<<<blocks, 256>>>(N, nchunks);

    reduce_norm_kernel<<<RB, 256>>>((float*)d_out, N);
}